// round 5
// baseline (speedup 1.0000x reference)
#include <cuda_runtime.h>
#include <cstdint>

#define B_    65536
#define FAN   1024
#define HIDN  512
#define G32   32

// K1 tiling: 128 threads, 1 row/thread, 128 rows/CTA -> grid 512
#define RPC    128
#define THR1   128
#define KC1    16
#define CPITCH 17      // odd pitch -> conflict-free scalar column reads
#define NCH    64      // 1024 / KC1

// K2 tiling
#define R2     128
#define CPF    8       // c-prefetch depth

typedef unsigned long long u64;

__device__ float g_z[(size_t)B_ * G32];   // z scratch [B][32]

__device__ __forceinline__ void ffma2(u64 &d, u64 a, u64 b) {
    asm volatile("fma.rn.f32x2 %0, %1, %2, %0;" : "+l"(d) : "l"(a), "l"(b));
}
__device__ __forceinline__ u64 dup2(float a) {
    u64 r; asm("mov.b64 %0, {%1, %1};" : "=l"(r) : "f"(a)); return r;
}
__device__ __forceinline__ float lo32(u64 v) { return __uint_as_float((unsigned)(v & 0xffffffffu)); }
__device__ __forceinline__ float hi32(u64 v) { return __uint_as_float((unsigned)(v >> 32)); }

__device__ __forceinline__ float tanh_ap(float x) {
    float y; asm("tanh.approx.f32 %0, %1;" : "=f"(y) : "f"(x)); return y;
}
__device__ __forceinline__ float tanh_acc(float x) {
    float e = __expf(-2.f * fabsf(x));
    float t = __fdividef(1.f - e, 1.f + e);
    return copysignf(t, x);
}

// ============================================================================
// K1: z[b,j] = tanh( sum_k comb[b,k]*W1[j,k] + b1[j] ), comb=[x|h], j in 0..31
// 128 threads, each owns one row. W chunk read as warp BROADCAST LDS.128;
// comb column read is scalar LDS with odd pitch (conflict-free).
// Double-buffered K=16 chunks. grid=512 -> good SM coverage.
// ============================================================================
__global__ void __launch_bounds__(THR1, 6)
k1_gemm1_tanh(const float* __restrict__ x, const float* __restrict__ hst,
              const float* __restrict__ W1, const float* __restrict__ b1)
{
    extern __shared__ float sm[];
    float* combS = sm;                        // [2][RPC][CPITCH]
    float* wS    = sm + 2 * RPC * CPITCH;     // [2][KC1][32]

    const int t    = threadIdx.x;
    const int row0 = blockIdx.x * RPC;

    float4 pc[4];
    float4 pw;

    auto stageLDG = [&](int ch) {
        const int kb = ch * KC1;
        const float* src = (kb < 512) ? x : hst;
        const int kcol   = (kb < 512) ? kb : kb - 512;
        #pragma unroll
        for (int i = 0; i < 4; i++) {
            int flat = i * THR1 + t;          // 0..511 float4s (128 rows x 4)
            int r = flat >> 2, kq = flat & 3;
            pc[i] = *reinterpret_cast<const float4*>(
                        &src[(size_t)(row0 + r) * 512 + kcol + kq * 4]);
        }
        {
            int j = t >> 2, kq = t & 3;       // j 0..31, kq 0..3
            pw = *reinterpret_cast<const float4*>(&W1[(size_t)j * FAN + kb + kq * 4]);
        }
    };
    auto stageSTS = [&](int buf) {
        float* cb = combS + buf * RPC * CPITCH;
        #pragma unroll
        for (int i = 0; i < 4; i++) {
            int flat = i * THR1 + t;
            int r = flat >> 2, kq = flat & 3;
            float* d = &cb[r * CPITCH + kq * 4];
            d[0] = pc[i].x; d[1] = pc[i].y; d[2] = pc[i].z; d[3] = pc[i].w;
        }
        {
            int j = t >> 2, kq = t & 3;
            float* wb = wS + buf * KC1 * 32;
            wb[(kq * 4 + 0) * 32 + j] = pw.x;
            wb[(kq * 4 + 1) * 32 + j] = pw.y;
            wb[(kq * 4 + 2) * 32 + j] = pw.z;
            wb[(kq * 4 + 3) * 32 + j] = pw.w;
        }
    };

    u64 acc[16];
    #pragma unroll
    for (int p = 0; p < 16; p++) acc[p] = 0ull;

    stageLDG(0);
    stageSTS(0);
    __syncthreads();

    for (int ch = 0; ch < NCH; ch++) {
        const int buf = ch & 1;
        if (ch + 1 < NCH) stageLDG(ch + 1);

        const float* cb = combS + buf * RPC * CPITCH;
        const float* wb = wS    + buf * KC1 * 32;
        #pragma unroll
        for (int k = 0; k < KC1; k++) {
            const u64 A0 = dup2(cb[t * CPITCH + k]);
            const ulonglong2* wp = reinterpret_cast<const ulonglong2*>(&wb[k * 32]);
            #pragma unroll
            for (int p = 0; p < 8; p++) {
                ulonglong2 wv = wp[p];        // broadcast LDS.128
                ffma2(acc[2 * p],     A0, wv.x);
                ffma2(acc[2 * p + 1], A0, wv.y);
            }
        }
        if (ch + 1 < NCH) stageSTS((ch + 1) & 1);
        __syncthreads();
    }

    // epilogue: bias + tanh + packed store (no bias array -> low reg pressure)
    const float2* b1v = reinterpret_cast<const float2*>(b1);
    float4* zp = reinterpret_cast<float4*>(&g_z[(size_t)(row0 + t) * G32]);
    #pragma unroll
    for (int v = 0; v < 8; v++) {
        float2 ba = __ldg(&b1v[2 * v]);
        float2 bb = __ldg(&b1v[2 * v + 1]);
        float o0 = tanh_acc(lo32(acc[2 * v])     + ba.x);
        float o1 = tanh_acc(hi32(acc[2 * v])     + ba.y);
        float o2 = tanh_acc(lo32(acc[2 * v + 1]) + bb.x);
        float o3 = tanh_acc(hi32(acc[2 * v + 1]) + bb.y);
        zp[v] = make_float4(o0, o1, o2, o3);
    }
}

// ============================================================================
// K2: gates = sigmoid(z@W2^T + b2); c_new = f*c+i*g; h_new = o*tanh(c_new)
// Thread <-> h-column; W2^T in 16 u64 regs for the whole kernel; z rows are
// smem broadcasts. c prefetched CPF=8 rows deep (cyclic reg buffer) to lift
// per-warp MLP from 1 to 8 -> removes the 577-cyc DRAM-latency serialization.
// sigma(x) = 0.5*tanh(0.5x)+0.5 via MUFU.TANH (5 MUFU/point).
// ============================================================================
__global__ void __launch_bounds__(512, 1)
k2_gates_cell(const float* __restrict__ c, const float* __restrict__ W2,
              const float* __restrict__ b2, float* __restrict__ out)
{
    __shared__ float zS[R2 * G32];           // 16 KB

    const int t    = threadIdx.x;            // == h column
    const int row0 = blockIdx.x * R2;

    u64 wu[16];
    float bh[4];
    #pragma unroll
    for (int g = 0; g < 4; g++) {
        const ulonglong2* p = reinterpret_cast<const ulonglong2*>(
                                  &W2[((size_t)g * HIDN + t) * 8]);
        ulonglong2 v0 = p[0], v1 = p[1];
        wu[g * 4 + 0] = v0.x; wu[g * 4 + 1] = v0.y;
        wu[g * 4 + 2] = v1.x; wu[g * 4 + 3] = v1.y;
        bh[g] = 0.5f * __ldg(&b2[(size_t)g * HIDN + t]);
    }

    #pragma unroll
    for (int i = 0; i < 2; i++) {
        int flat = i * 512 + t;
        *reinterpret_cast<float4*>(&zS[flat * 4]) =
            *reinterpret_cast<const float4*>(&g_z[(size_t)row0 * G32 + flat * 4]);
    }
    __syncthreads();

    const float* cp = c   + (size_t)row0 * HIDN + t;
    float*       o1 = out + (size_t)row0 * HIDN + t;
    float*       o2 = o1  + (size_t)B_ * HIDN;

    float cbuf[CPF];
    #pragma unroll
    for (int i = 0; i < CPF; i++) cbuf[i] = cp[(size_t)i * HIDN];

    #pragma unroll 8
    for (int r = 0; r < R2; r++) {
        const float cv = cbuf[r & (CPF - 1)];
        if (r + CPF < R2)
            cbuf[r & (CPF - 1)] = cp[(size_t)(r + CPF) * HIDN];

        const ulonglong2* zp = reinterpret_cast<const ulonglong2*>(&zS[r * G32]);
        float pre[4];
        #pragma unroll
        for (int g = 0; g < 4; g++) {
            ulonglong2 z0 = zp[2 * g], z1 = zp[2 * g + 1];   // broadcast LDS.128
            u64 a = 0ull;
            ffma2(a, z0.x, wu[g * 4 + 0]);
            ffma2(a, z0.y, wu[g * 4 + 1]);
            ffma2(a, z1.x, wu[g * 4 + 2]);
            ffma2(a, z1.y, wu[g * 4 + 3]);
            pre[g] = lo32(a) + hi32(a);
        }

        const float gi = fmaf(0.5f, tanh_ap(fmaf(0.5f, pre[0], bh[0])), 0.5f);
        const float gf = fmaf(0.5f, tanh_ap(fmaf(0.5f, pre[1], bh[1])), 0.5f);
        const float go = fmaf(0.5f, tanh_ap(fmaf(0.5f, pre[2], bh[2])), 0.5f);
        const float gg = fmaf(0.5f, tanh_ap(fmaf(0.5f, pre[3], bh[3])), 0.5f);

        const float cn = fmaf(gf, cv, gi * gg);
        const float hn = go * tanh_ap(cn);

        o1[(size_t)r * HIDN] = hn;
        o2[(size_t)r * HIDN] = cn;
    }
}

extern "C" void kernel_launch(void* const* d_in, const int* in_sizes, int n_in,
                              void* d_out, int out_size)
{
    const float* x  = (const float*)d_in[0];
    const float* h  = (const float*)d_in[1];
    const float* c  = (const float*)d_in[2];
    const float* W1 = (const float*)d_in[3];
    const float* b1 = (const float*)d_in[4];
    const float* W2 = (const float*)d_in[5];
    const float* b2 = (const float*)d_in[6];
    float* out = (float*)d_out;

    const int smem1 = (2 * RPC * CPITCH + 2 * KC1 * 32) * sizeof(float);  // 21504 B

    k1_gemm1_tanh<<<B_ / RPC, THR1, smem1>>>(x, h, W1, b1);
    k2_gates_cell<<<B_ / R2, 512>>>(c, W2, b2, out);
}

// round 7
// speedup vs baseline: 1.0706x; 1.0706x over previous
#include <cuda_runtime.h>
#include <cstdint>

#define B_    65536
#define FAN   1024
#define HIDN  512
#define G32   32

// K1: 256 threads, 1 row/thread, 256 rows/CTA -> grid 256, 3 CTAs/SM
#define RPC    256
#define THR1   256
#define KC1    16
#define CPITCH 17      // odd pitch -> conflict-free scalar column reads
#define NCH    64      // 1024 / KC1

// K2: 256 threads, 128 rows x 256 h-cols per CTA -> grid 1024, 2 CTAs/SM
#define R2     128
#define HC2    256
#define CPF    8       // c-prefetch depth

typedef unsigned long long u64;

__device__ float g_z[(size_t)B_ * G32];   // z scratch [B][32]

__device__ __forceinline__ void ffma2(u64 &d, u64 a, u64 b) {
    asm volatile("fma.rn.f32x2 %0, %1, %2, %0;" : "+l"(d) : "l"(a), "l"(b));
}
__device__ __forceinline__ u64 dup2(float a) {
    u64 r; asm("mov.b64 %0, {%1, %1};" : "=l"(r) : "f"(a)); return r;
}
__device__ __forceinline__ float lo32(u64 v) { return __uint_as_float((unsigned)(v & 0xffffffffu)); }
__device__ __forceinline__ float hi32(u64 v) { return __uint_as_float((unsigned)(v >> 32)); }

__device__ __forceinline__ float tanh_ap(float x) {
    float y; asm("tanh.approx.f32 %0, %1;" : "=f"(y) : "f"(x)); return y;
}
__device__ __forceinline__ float tanh_acc(float x) {
    float e = __expf(-2.f * fabsf(x));
    float t = __fdividef(1.f - e, 1.f + e);
    return copysignf(t, x);
}
__device__ __forceinline__ void stcs(float* p, float v) {
    asm volatile("st.global.cs.f32 [%0], %1;" :: "l"(p), "f"(v) : "memory");
}

// ============================================================================
// K1: z[b,j] = tanh( sum_k comb[b,k]*W1[j,k] + b1[j] ), comb=[x|h], j in 0..31
// 256 threads, 1 row each. W chunk = warp-broadcast LDS.128; comb column =
// scalar LDS, odd pitch (conflict-free). Double-buffered K=16 chunks.
// 3 CTAs/SM (reg cap 85; live set ~60), all 256 CTAs resident in one wave.
// ============================================================================
__global__ void __launch_bounds__(THR1, 3)
k1_gemm1_tanh(const float* __restrict__ x, const float* __restrict__ hst,
              const float* __restrict__ W1, const float* __restrict__ b1)
{
    extern __shared__ float sm[];
    float* combS = sm;                        // [2][RPC][CPITCH]
    float* wS    = sm + 2 * RPC * CPITCH;     // [2][KC1][32]

    const int t    = threadIdx.x;
    const int row0 = blockIdx.x * RPC;

    float4 pc[4];
    float4 pw;

    auto stageLDG = [&](int ch) {
        const int kb = ch * KC1;
        const float* src = (kb < 512) ? x : hst;
        const int kcol   = (kb < 512) ? kb : kb - 512;
        #pragma unroll
        for (int i = 0; i < 4; i++) {
            int flat = i * THR1 + t;          // 0..1023 float4s (256 rows x 4)
            int r = flat >> 2, kq = flat & 3;
            pc[i] = *reinterpret_cast<const float4*>(
                        &src[(size_t)(row0 + r) * 512 + kcol + kq * 4]);
        }
        if (t < 128) {
            int j = t >> 2, kq = t & 3;       // j 0..31, kq 0..3
            pw = *reinterpret_cast<const float4*>(&W1[(size_t)j * FAN + kb + kq * 4]);
        }
    };
    auto stageSTS = [&](int buf) {
        float* cb = combS + buf * RPC * CPITCH;
        #pragma unroll
        for (int i = 0; i < 4; i++) {
            int flat = i * THR1 + t;
            int r = flat >> 2, kq = flat & 3;
            float* d = &cb[r * CPITCH + kq * 4];
            d[0] = pc[i].x; d[1] = pc[i].y; d[2] = pc[i].z; d[3] = pc[i].w;
        }
        if (t < 128) {
            int j = t >> 2, kq = t & 3;
            float* wb = wS + buf * KC1 * 32;
            wb[(kq * 4 + 0) * 32 + j] = pw.x;
            wb[(kq * 4 + 1) * 32 + j] = pw.y;
            wb[(kq * 4 + 2) * 32 + j] = pw.z;
            wb[(kq * 4 + 3) * 32 + j] = pw.w;
        }
    };

    u64 acc[16];
    #pragma unroll
    for (int p = 0; p < 16; p++) acc[p] = 0ull;

    stageLDG(0);
    stageSTS(0);
    __syncthreads();

    for (int ch = 0; ch < NCH; ch++) {
        const int buf = ch & 1;
        if (ch + 1 < NCH) stageLDG(ch + 1);

        const float* cb = combS + buf * RPC * CPITCH;
        const float* wb = wS    + buf * KC1 * 32;
        #pragma unroll
        for (int k = 0; k < KC1; k++) {
            const u64 A0 = dup2(cb[t * CPITCH + k]);
            const ulonglong2* wp = reinterpret_cast<const ulonglong2*>(&wb[k * 32]);
            #pragma unroll
            for (int p = 0; p < 8; p++) {
                ulonglong2 wv = wp[p];        // broadcast LDS.128
                ffma2(acc[2 * p],     A0, wv.x);
                ffma2(acc[2 * p + 1], A0, wv.y);
            }
        }
        if (ch + 1 < NCH) stageSTS((ch + 1) & 1);
        __syncthreads();
    }

    // epilogue: bias + tanh + packed store (biases re-read pairwise, low regs)
    const float2* b1v = reinterpret_cast<const float2*>(b1);
    float4* zp = reinterpret_cast<float4*>(&g_z[(size_t)(row0 + t) * G32]);
    #pragma unroll
    for (int v = 0; v < 8; v++) {
        float2 ba = __ldg(&b1v[2 * v]);
        float2 bb = __ldg(&b1v[2 * v + 1]);
        float o0 = tanh_acc(lo32(acc[2 * v])     + ba.x);
        float o1 = tanh_acc(hi32(acc[2 * v])     + ba.y);
        float o2 = tanh_acc(lo32(acc[2 * v + 1]) + bb.x);
        float o3 = tanh_acc(hi32(acc[2 * v + 1]) + bb.y);
        zp[v] = make_float4(o0, o1, o2, o3);
    }
}

// ============================================================================
// K2: gates = sigmoid(z@W2^T + b2); c_new = f*c+i*g; h_new = o*tanh(c_new)
// CTA = 128 rows x 256 h-cols, 256 threads (thread <-> h-col). W2^T lives in
// 16 u64 regs; z rows broadcast from smem; c prefetched 8 deep; streaming
// stores. 2 CTAs/SM -> 32 warps (double R5's concurrency).
// ============================================================================
__global__ void __launch_bounds__(256, 2)
k2_gates_cell(const float* __restrict__ c, const float* __restrict__ W2,
              const float* __restrict__ b2, float* __restrict__ out)
{
    __shared__ float zS[R2 * G32];           // 16 KB

    const int t    = threadIdx.x;
    const int row0 = (blockIdx.x >> 1) * R2;
    const int hcol = (blockIdx.x & 1) * HC2 + t;

    u64 wu[16];
    float bh[4];
    #pragma unroll
    for (int g = 0; g < 4; g++) {
        const ulonglong2* p = reinterpret_cast<const ulonglong2*>(
                                  &W2[((size_t)g * HIDN + hcol) * 8]);
        ulonglong2 v0 = p[0], v1 = p[1];
        wu[g * 4 + 0] = v0.x; wu[g * 4 + 1] = v0.y;
        wu[g * 4 + 2] = v1.x; wu[g * 4 + 3] = v1.y;
        bh[g] = 0.5f * __ldg(&b2[(size_t)g * HIDN + hcol]);
    }

    // stage z tile [R2][32] (coalesced; both column-CTAs read the same tile)
    #pragma unroll
    for (int i = 0; i < 4; i++) {
        int flat = i * 256 + t;              // 0..1023 float4s
        *reinterpret_cast<float4*>(&zS[flat * 4]) =
            *reinterpret_cast<const float4*>(&g_z[(size_t)row0 * G32 + flat * 4]);
    }
    __syncthreads();

    const float* cp = c   + (size_t)row0 * HIDN + hcol;
    float*       o1 = out + (size_t)row0 * HIDN + hcol;
    float*       o2 = o1  + (size_t)B_ * HIDN;

    float cbuf[CPF];
    #pragma unroll
    for (int i = 0; i < CPF; i++) cbuf[i] = cp[(size_t)i * HIDN];

    #pragma unroll 8
    for (int r = 0; r < R2; r++) {
        const float cv = cbuf[r & (CPF - 1)];
        if (r + CPF < R2)
            cbuf[r & (CPF - 1)] = cp[(size_t)(r + CPF) * HIDN];

        const ulonglong2* zp = reinterpret_cast<const ulonglong2*>(&zS[r * G32]);
        float pre[4];
        #pragma unroll
        for (int g = 0; g < 4; g++) {
            ulonglong2 z0 = zp[2 * g], z1 = zp[2 * g + 1];   // broadcast LDS.128
            u64 a = 0ull;
            ffma2(a, z0.x, wu[g * 4 + 0]);
            ffma2(a, z0.y, wu[g * 4 + 1]);
            ffma2(a, z1.x, wu[g * 4 + 2]);
            ffma2(a, z1.y, wu[g * 4 + 3]);
            pre[g] = lo32(a) + hi32(a);
        }

        const float gi = fmaf(0.5f, tanh_ap(fmaf(0.5f, pre[0], bh[0])), 0.5f);
        const float gf = fmaf(0.5f, tanh_ap(fmaf(0.5f, pre[1], bh[1])), 0.5f);
        const float go = fmaf(0.5f, tanh_ap(fmaf(0.5f, pre[2], bh[2])), 0.5f);
        const float gg = fmaf(0.5f, tanh_ap(fmaf(0.5f, pre[3], bh[3])), 0.5f);

        const float cn = fmaf(gf, cv, gi * gg);
        const float hn = go * tanh_ap(cn);

        stcs(&o1[(size_t)r * HIDN], hn);
        stcs(&o2[(size_t)r * HIDN], cn);
    }
}

extern "C" void kernel_launch(void* const* d_in, const int* in_sizes, int n_in,
                              void* d_out, int out_size)
{
    const float* x  = (const float*)d_in[0];
    const float* h  = (const float*)d_in[1];
    const float* c  = (const float*)d_in[2];
    const float* W1 = (const float*)d_in[3];
    const float* b1 = (const float*)d_in[4];
    const float* W2 = (const float*)d_in[5];
    const float* b2 = (const float*)d_in[6];
    float* out = (float*)d_out;

    const int smem1 = (2 * RPC * CPITCH + 2 * KC1 * 32) * sizeof(float);  // 38912 B

    k1_gemm1_tanh<<<B_ / RPC, THR1, smem1>>>(x, h, W1, b1);
    k2_gates_cell<<<(B_ / R2) * 2, 256>>>(c, W2, b2, out);
}

// round 12
// speedup vs baseline: 1.0752x; 1.0043x over previous
#include <cuda_runtime.h>
#include <cstdint>

#define B_    65536
#define FAN   1024
#define HIDN  512
#define G32   32

// K1: 128 threads, 2 rows/thread, 256 rows/CTA -> grid 256, 4 CTAs/SM
#define THR1   128
#define RPC    256
#define KC1    8
#define CPITCH 9       // odd pitch -> conflict-free scalar column reads
#define NCH    128     // 1024 / KC1

// K2: 256 threads, 128 rows x 256 h-cols per CTA -> grid 1024, 3 CTAs/SM
#define R2     128
#define HC2    256
#define CPF    4       // c-prefetch depth (power of 2)

typedef unsigned long long u64;

__device__ float g_z[(size_t)B_ * G32];   // z scratch [B][32]

__device__ __forceinline__ void ffma2(u64 &d, u64 a, u64 b) {
    asm volatile("fma.rn.f32x2 %0, %1, %2, %0;" : "+l"(d) : "l"(a), "l"(b));
}
__device__ __forceinline__ u64 dup2(float a) {
    u64 r; asm("mov.b64 %0, {%1, %1};" : "=l"(r) : "f"(a)); return r;
}
__device__ __forceinline__ float lo32(u64 v) { return __uint_as_float((unsigned)(v & 0xffffffffu)); }
__device__ __forceinline__ float hi32(u64 v) { return __uint_as_float((unsigned)(v >> 32)); }

__device__ __forceinline__ float tanh_ap(float x) {
    float y; asm("tanh.approx.f32 %0, %1;" : "=f"(y) : "f"(x)); return y;
}
__device__ __forceinline__ void stcs(float* p, float v) {
    asm volatile("st.global.cs.f32 [%0], %1;" :: "l"(p), "f"(v) : "memory");
}

// ============================================================================
// K1: z[b,j] = tanh( sum_k comb[b,k]*W1[j,k] + b1[j] ), comb=[x|h], j in 0..31
// 128 threads, 2 rows each (t, t+128). Per k: 2 scalar A-LDS + 8 broadcast
// W-LDS.128 feed 32 FFMA2 (rt~2 -> 64 fma-cyc): W-read redundancy halved vs
// 1-row/thread. KC=8 double-buffered chunks; smem 20.5KB -> 4 CTAs/SM,
// reg cap 128 (no spill).
// ============================================================================
__global__ void __launch_bounds__(THR1, 4)
k1_gemm1_tanh(const float* __restrict__ x, const float* __restrict__ hst,
              const float* __restrict__ W1, const float* __restrict__ b1)
{
    __shared__ float combS[2 * RPC * CPITCH];   // [2][256][9]
    __shared__ float wS[2 * KC1 * 32];          // [2][8][32]

    const int t    = threadIdx.x;
    const int row0 = blockIdx.x * RPC;

    float4 pc[4];
    float4 pw;

    auto stageLDG = [&](int ch) {
        const int kb = ch * KC1;
        const float* src = (kb < 512) ? x : hst;
        const int kcol   = (kb < 512) ? kb : kb - 512;
        #pragma unroll
        for (int i = 0; i < 4; i++) {
            int flat = i * THR1 + t;           // 0..511 float4s (256 rows x 2)
            int r = flat >> 1, kq = flat & 1;
            pc[i] = *reinterpret_cast<const float4*>(
                        &src[(size_t)(row0 + r) * 512 + kcol + kq * 4]);
        }
        if (t < 64) {
            int j = t >> 1, kq = t & 1;        // j 0..31, kq 0..1
            pw = *reinterpret_cast<const float4*>(&W1[(size_t)j * FAN + kb + kq * 4]);
        }
    };
    auto stageSTS = [&](int buf) {
        float* cb = combS + buf * RPC * CPITCH;
        #pragma unroll
        for (int i = 0; i < 4; i++) {
            int flat = i * THR1 + t;
            int r = flat >> 1, kq = flat & 1;
            float* d = &cb[r * CPITCH + kq * 4];
            d[0] = pc[i].x; d[1] = pc[i].y; d[2] = pc[i].z; d[3] = pc[i].w;
        }
        if (t < 64) {
            int j = t >> 1, kq = t & 1;
            float* wb = wS + buf * KC1 * 32;
            wb[(kq * 4 + 0) * 32 + j] = pw.x;
            wb[(kq * 4 + 1) * 32 + j] = pw.y;
            wb[(kq * 4 + 2) * 32 + j] = pw.z;
            wb[(kq * 4 + 3) * 32 + j] = pw.w;
        }
    };

    u64 acc0[16], acc1[16];
    #pragma unroll
    for (int p = 0; p < 16; p++) { acc0[p] = 0ull; acc1[p] = 0ull; }

    stageLDG(0);
    stageSTS(0);
    __syncthreads();

    for (int ch = 0; ch < NCH; ch++) {
        const int buf = ch & 1;
        if (ch + 1 < NCH) stageLDG(ch + 1);

        const float* cb = combS + buf * RPC * CPITCH;
        const float* wb = wS    + buf * KC1 * 32;
        #pragma unroll
        for (int k = 0; k < KC1; k++) {
            const u64 A0 = dup2(cb[t * CPITCH + k]);
            const u64 A1 = dup2(cb[(t + THR1) * CPITCH + k]);
            const ulonglong2* wp = reinterpret_cast<const ulonglong2*>(&wb[k * 32]);
            #pragma unroll
            for (int p = 0; p < 8; p++) {
                ulonglong2 wv = wp[p];         // broadcast LDS.128
                ffma2(acc0[2 * p],     A0, wv.x);
                ffma2(acc0[2 * p + 1], A0, wv.y);
                ffma2(acc1[2 * p],     A1, wv.x);
                ffma2(acc1[2 * p + 1], A1, wv.y);
            }
        }
        if (ch + 1 < NCH) stageSTS((ch + 1) & 1);
        __syncthreads();
    }

    // epilogue: bias + tanh.approx + packed stores
    const float2* b1v = reinterpret_cast<const float2*>(b1);
    #pragma unroll
    for (int rr = 0; rr < 2; rr++) {
        const u64* ac = rr ? acc1 : acc0;
        float4* zp = reinterpret_cast<float4*>(&g_z[(size_t)(row0 + t + rr * THR1) * G32]);
        #pragma unroll
        for (int v = 0; v < 8; v++) {
            float2 ba = __ldg(&b1v[2 * v]);
            float2 bb = __ldg(&b1v[2 * v + 1]);
            float o0 = tanh_ap(lo32(ac[2 * v])     + ba.x);
            float o1 = tanh_ap(hi32(ac[2 * v])     + ba.y);
            float o2 = tanh_ap(lo32(ac[2 * v + 1]) + bb.x);
            float o3 = tanh_ap(hi32(ac[2 * v + 1]) + bb.y);
            zp[v] = make_float4(o0, o1, o2, o3);
        }
    }
}

// ============================================================================
// K2: gates = sigmoid(z@W2^T + b2); c_new = f*c+i*g; h_new = o*tanh(c_new)
// CTA = 128 rows x 256 h-cols, 256 threads (thread <-> h-col). W2^T in 16 u64
// regs; z rows broadcast from smem; c prefetched 4 deep; streaming stores.
// Reg cap 85 (launch_bounds 256,3) -> 3 CTAs/SM = 24 warps.
// ============================================================================
__global__ void __launch_bounds__(256, 3)
k2_gates_cell(const float* __restrict__ c, const float* __restrict__ W2,
              const float* __restrict__ b2, float* __restrict__ out)
{
    __shared__ float zS[R2 * G32];           // 16 KB

    const int t    = threadIdx.x;
    const int row0 = (blockIdx.x >> 1) * R2;
    const int hcol = (blockIdx.x & 1) * HC2 + t;

    u64 wu[16];
    float bh[4];
    #pragma unroll
    for (int g = 0; g < 4; g++) {
        const ulonglong2* p = reinterpret_cast<const ulonglong2*>(
                                  &W2[((size_t)g * HIDN + hcol) * 8]);
        ulonglong2 v0 = p[0], v1 = p[1];
        wu[g * 4 + 0] = v0.x; wu[g * 4 + 1] = v0.y;
        wu[g * 4 + 2] = v1.x; wu[g * 4 + 3] = v1.y;
        bh[g] = 0.5f * __ldg(&b2[(size_t)g * HIDN + hcol]);
    }

    // stage z tile [R2][32] (coalesced; both column-CTAs read the same tile)
    #pragma unroll
    for (int i = 0; i < 4; i++) {
        int flat = i * 256 + t;              // 0..1023 float4s
        *reinterpret_cast<float4*>(&zS[flat * 4]) =
            *reinterpret_cast<const float4*>(&g_z[(size_t)row0 * G32 + flat * 4]);
    }
    __syncthreads();

    const float* cp = c   + (size_t)row0 * HIDN + hcol;
    float*       o1 = out + (size_t)row0 * HIDN + hcol;
    float*       o2 = o1  + (size_t)B_ * HIDN;

    float cbuf[CPF];
    #pragma unroll
    for (int i = 0; i < CPF; i++) cbuf[i] = cp[(size_t)i * HIDN];

    #pragma unroll 4
    for (int r = 0; r < R2; r++) {
        const float cv = cbuf[r & (CPF - 1)];
        if (r + CPF < R2)
            cbuf[r & (CPF - 1)] = cp[(size_t)(r + CPF) * HIDN];

        const ulonglong2* zp = reinterpret_cast<const ulonglong2*>(&zS[r * G32]);
        float pre[4];
        #pragma unroll
        for (int g = 0; g < 4; g++) {
            ulonglong2 z0 = zp[2 * g], z1 = zp[2 * g + 1];   // broadcast LDS.128
            u64 a = 0ull;
            ffma2(a, z0.x, wu[g * 4 + 0]);
            ffma2(a, z0.y, wu[g * 4 + 1]);
            ffma2(a, z1.x, wu[g * 4 + 2]);
            ffma2(a, z1.y, wu[g * 4 + 3]);
            pre[g] = lo32(a) + hi32(a);
        }

        const float gi = fmaf(0.5f, tanh_ap(fmaf(0.5f, pre[0], bh[0])), 0.5f);
        const float gf = fmaf(0.5f, tanh_ap(fmaf(0.5f, pre[1], bh[1])), 0.5f);
        const float go = fmaf(0.5f, tanh_ap(fmaf(0.5f, pre[2], bh[2])), 0.5f);
        const float gg = fmaf(0.5f, tanh_ap(fmaf(0.5f, pre[3], bh[3])), 0.5f);

        const float cn = fmaf(gf, cv, gi * gg);
        const float hn = go * tanh_ap(cn);

        stcs(&o1[(size_t)r * HIDN], hn);
        stcs(&o2[(size_t)r * HIDN], cn);
    }
}

extern "C" void kernel_launch(void* const* d_in, const int* in_sizes, int n_in,
                              void* d_out, int out_size)
{
    const float* x  = (const float*)d_in[0];
    const float* h  = (const float*)d_in[1];
    const float* c  = (const float*)d_in[2];
    const float* W1 = (const float*)d_in[3];
    const float* b1 = (const float*)d_in[4];
    const float* W2 = (const float*)d_in[5];
    const float* b2 = (const float*)d_in[6];
    float* out = (float*)d_out;

    k1_gemm1_tanh<<<B_ / RPC, THR1>>>(x, h, W1, b1);
    k2_gates_cell<<<(B_ / R2) * 2, 256>>>(c, W2, b2, out);
}